// round 1
// baseline (speedup 1.0000x reference)
#include <cuda_runtime.h>
#include <math.h>

#define B_TOTAL 65536
#define NL 7
#define ZDIM 14
#define DDIM 32
#define HDIM 64

// ---- scratch (static device globals: allocation-free rule) ----
__device__ float g_traces[(size_t)B_TOTAL * NL * DDIM];   // 58.7 MB
__device__ float g_gates[(size_t)B_TOTAL * NL];           // 1.8 MB

// Fano ordered pairs: src = FANO[l][p], par = FANO[l][(p+1)%3]
__constant__ int FSRC[21] = {0,1,2, 0,3,4, 0,5,6, 1,3,5, 1,4,6, 2,3,6, 2,4,5};
__constant__ int FPAR[21] = {1,2,0, 3,4,0, 5,6,0, 3,5,1, 4,6,1, 3,6,2, 4,5,2};

__device__ __forceinline__ float warp_sum(float v) {
#pragma unroll
    for (int o = 16; o > 0; o >>= 1) v += __shfl_xor_sync(0xffffffffu, v, o);
    return v;
}

__device__ __forceinline__ float colony_act(int c, float x) {
    switch (c) {
        case 0: return fmaxf(x, 0.0f);                                   // relu
        case 1: return tanhf(x);                                          // tanh
        case 2: return 0.5f * x * (1.0f + erff(x * 0.7071067811865476f)); // exact gelu
        case 3: return x / (1.0f + expf(-x));                             // silu
        case 4: return fmaxf(x, 0.0f) + log1pf(expf(-fabsf(x)));          // softplus
        case 5: return 1.0f / (1.0f + expf(-x));                          // sigmoid
        default: return fminf(fmaxf(x, -1.0f), 1.0f);                     // clip
    }
}

// ============================================================================
// Kernel 1: per-colony trace generator + confidence + gates + comp_conf
// SMEM weights (floats):
//  W1 6272 | b1 448 | g 448 | be 448 | W2 14336 | b2 224 |
//  cfW1 3136 | cfb1 224 | cfW2 224 | cfb2 8 | gW 1568 | gb 8  = 27344
// per-warp scratch: z 100 + a 64 + tr 224 + conf 8 + gate 8 + pad = 408
// ============================================================================
#define K1_WSZ 27344
#define K1_SCR 408
#define K1_WARPS 16
#define K1_SMEM ((K1_WSZ + K1_WARPS * K1_SCR) * 4)

__global__ void __launch_bounds__(512, 1)
colony_k1(const float* __restrict__ z,
          const float* __restrict__ gen_W1, const float* __restrict__ gen_b1,
          const float* __restrict__ gen_g,  const float* __restrict__ gen_be,
          const float* __restrict__ gen_W2, const float* __restrict__ gen_b2,
          const float* __restrict__ cf_W1,  const float* __restrict__ cf_b1,
          const float* __restrict__ cf_W2,  const float* __restrict__ cf_b2,
          const float* __restrict__ gw,     const float* __restrict__ gb,
          float* __restrict__ out_conf)
{
    extern __shared__ float sm[];
    float* sW1  = sm;            // 6272
    float* sb1  = sW1  + 6272;   // 448
    float* sg   = sb1  + 448;    // 448
    float* sbe  = sg   + 448;    // 448
    float* sW2  = sbe  + 448;    // 14336
    float* sb2  = sW2  + 14336;  // 224
    float* scW1 = sb2  + 224;    // 3136
    float* scb1 = scW1 + 3136;   // 224
    float* scW2 = scb1 + 224;    // 224
    float* scb2 = scW2 + 224;    // 8 (7 used)
    float* sgW  = scb2 + 8;      // 1568
    float* sgb  = sgW  + 1568;   // 8 (7 used)
    float* sscr = sgb  + 8;

    const int tid = threadIdx.x;
    for (int i = tid; i < 6272;  i += blockDim.x) sW1[i]  = gen_W1[i];
    for (int i = tid; i < 448;   i += blockDim.x) sb1[i]  = gen_b1[i];
    for (int i = tid; i < 448;   i += blockDim.x) sg[i]   = gen_g[i];
    for (int i = tid; i < 448;   i += blockDim.x) sbe[i]  = gen_be[i];
    for (int i = tid; i < 14336; i += blockDim.x) sW2[i]  = gen_W2[i];
    for (int i = tid; i < 224;   i += blockDim.x) sb2[i]  = gen_b2[i];
    for (int i = tid; i < 3136;  i += blockDim.x) scW1[i] = cf_W1[i];
    for (int i = tid; i < 224;   i += blockDim.x) scb1[i] = cf_b1[i];
    for (int i = tid; i < 224;   i += blockDim.x) scW2[i] = cf_W2[i];
    for (int i = tid; i < 7;     i += blockDim.x) scb2[i] = cf_b2[i];
    for (int i = tid; i < 1568;  i += blockDim.x) sgW[i]  = gw[i];
    for (int i = tid; i < 7;     i += blockDim.x) sgb[i]  = gb[i];
    __syncthreads();

    const int wid  = tid >> 5;
    const int lane = tid & 31;
    float* wz    = sscr + wid * K1_SCR;   // 100 (98 used)
    float* wa    = wz + 100;              // 64
    float* wtr   = wa + 64;               // 224
    float* wconf = wtr + 224;             // 8
    float* wgate = wconf + 8;             // 8

    const int warps_per_block = blockDim.x >> 5;
    const int gwarp = blockIdx.x * warps_per_block + wid;
    const int nwarp = gridDim.x * warps_per_block;

    for (int b = gwarp; b < B_TOTAL; b += nwarp) {
        const float* zb = z + (size_t)b * (NL * ZDIM);
        for (int i = lane; i < NL * ZDIM; i += 32) wz[i] = zb[i];
        __syncwarp();

#pragma unroll
        for (int c = 0; c < NL; c++) {
            // ---- h = z @ W1 + b1 ----
            float h0 = sb1[c * 64 + lane];
            float h1 = sb1[c * 64 + 32 + lane];
            const float* w1c = sW1 + c * (14 * 64);
            const float* zc  = wz + c * 14;
#pragma unroll
            for (int q = 0; q < 14; q++) {
                float zv = zc[q];
                h0 = fmaf(zv, w1c[q * 64 + lane], h0);
                h1 = fmaf(zv, w1c[q * 64 + 32 + lane], h1);
            }
            // ---- LayerNorm over 64 ----
            float m = warp_sum(h0 + h1) * (1.0f / 64.0f);
            float d0 = h0 - m, d1 = h1 - m;
            float var = warp_sum(d0 * d0 + d1 * d1) * (1.0f / 64.0f);
            float inv = rsqrtf(var + 1e-5f);
            float a0 = colony_act(c, d0 * inv * sg[c * 64 + lane] + sbe[c * 64 + lane]);
            float a1 = colony_act(c, d1 * inv * sg[c * 64 + 32 + lane] + sbe[c * 64 + 32 + lane]);
            wa[lane] = a0; wa[lane + 32] = a1;
            __syncwarp();
            // ---- traces = a @ W2 + b2, l2norm ----
            float t = sb2[c * 32 + lane];
            const float* w2c = sW2 + c * (64 * 32);
#pragma unroll
            for (int hh = 0; hh < 64; hh++) t = fmaf(wa[hh], w2c[hh * 32 + lane], t);
            float nrm = sqrtf(warp_sum(t * t));
            t = t / fmaxf(nrm, 1e-12f);
            wtr[c * 32 + lane] = t;
            g_traces[(size_t)b * 224 + c * 32 + lane] = t;
            // ---- confidence head ----
            float hc = scb1[c * 32 + lane];
            const float* cw1 = scW1 + c * (14 * 32);
#pragma unroll
            for (int q = 0; q < 14; q++) hc = fmaf(zc[q], cw1[q * 32 + lane], hc);
            hc = fmaxf(hc, 0.0f);
            float s = warp_sum(hc * scW2[c * 32 + lane]);
            if (lane == 0) wconf[c] = 1.0f / (1.0f + expf(-(s + scb2[c])));
            __syncwarp();
        }

        // ---- gates = sigmoid(traces_flat @ gW + gb) ----
#pragma unroll
        for (int l = 0; l < NL; l++) {
            float p = 0.0f;
#pragma unroll
            for (int k = 0; k < 7; k++) {
                int i = lane + 32 * k;
                p = fmaf(wtr[i], sgW[i * 7 + l], p);
            }
            p = warp_sum(p);
            if (lane == 0) wgate[l] = 1.0f / (1.0f + expf(-(p + sgb[l])));
        }
        __syncwarp();
        if (lane < 7) g_gates[(size_t)b * 7 + lane] = wgate[lane];
        // ---- comp_conf = active ? conf[src]*conf[par]*gate : 0 ----
        if (lane < 21) {
            int l = lane / 3;
            float gl = wgate[l];
            float v = (gl >= 0.3f) ? wconf[FSRC[lane]] * wconf[FPAR[lane]] * gl : 0.0f;
            out_conf[(size_t)b * 21 + lane] = v;
        }
        __syncwarp();
    }
}

// ============================================================================
// Kernel 2: line composers
// SMEM weights: cW1 28672 | cb1 448 | cg 448 | cbe 448 | cW2 14336 | cb2 224
//             = 44576 floats. per-warp scratch: tr 224 + ch 64 + g 8 = 296
// ============================================================================
#define K2_WSZ 44576
#define K2_SCR 296
#define K2_WARPS 16
#define K2_SMEM ((K2_WSZ + K2_WARPS * K2_SCR) * 4)

__global__ void __launch_bounds__(512, 1)
colony_k2(const float* __restrict__ cW1, const float* __restrict__ cb1,
          const float* __restrict__ cg,  const float* __restrict__ cbe,
          const float* __restrict__ cW2, const float* __restrict__ cb2,
          float* __restrict__ out)
{
    extern __shared__ float sm[];
    float* sW1 = sm;            // 28672
    float* sb1 = sW1 + 28672;   // 448
    float* sg  = sb1 + 448;     // 448
    float* sbe = sg  + 448;     // 448
    float* sW2 = sbe + 448;     // 14336
    float* sb2 = sW2 + 14336;   // 224
    float* sscr = sb2 + 224;

    const int tid = threadIdx.x;
    for (int i = tid; i < 28672; i += blockDim.x) sW1[i] = cW1[i];
    for (int i = tid; i < 448;   i += blockDim.x) sb1[i] = cb1[i];
    for (int i = tid; i < 448;   i += blockDim.x) sg[i]  = cg[i];
    for (int i = tid; i < 448;   i += blockDim.x) sbe[i] = cbe[i];
    for (int i = tid; i < 14336; i += blockDim.x) sW2[i] = cW2[i];
    for (int i = tid; i < 224;   i += blockDim.x) sb2[i] = cb2[i];
    __syncthreads();

    const int wid  = tid >> 5;
    const int lane = tid & 31;
    float* wtr = sscr + wid * K2_SCR;  // 224
    float* wch = wtr + 224;            // 64
    float* wg  = wch + 64;             // 8

    const int warps_per_block = blockDim.x >> 5;
    const int gwarp = blockIdx.x * warps_per_block + wid;
    const int nwarp = gridDim.x * warps_per_block;

    for (int b = gwarp; b < B_TOTAL; b += nwarp) {
        for (int i = lane; i < 224; i += 32) wtr[i] = g_traces[(size_t)b * 224 + i];
        if (lane < 7) wg[lane] = g_gates[(size_t)b * 7 + lane];
        __syncwarp();

#pragma unroll
        for (int l = 0; l < NL; l++) {
            float gl = wg[l];
            float scale = (gl >= 0.3f) ? gl : 0.0f;
            const float* W1l = sW1 + l * (64 * 64);
            const float* W2l = sW2 + l * (64 * 32);
#pragma unroll
            for (int p = 0; p < 3; p++) {
                const float* ta = wtr + FSRC[l * 3 + p] * 32;
                const float* tb = wtr + FPAR[l * 3 + p] * 32;
                float h0 = sb1[l * 64 + lane];
                float h1 = sb1[l * 64 + 32 + lane];
#pragma unroll
                for (int i = 0; i < 32; i++) {
                    float v = ta[i];
                    h0 = fmaf(v, W1l[i * 64 + lane], h0);
                    h1 = fmaf(v, W1l[i * 64 + 32 + lane], h1);
                }
#pragma unroll
                for (int i = 0; i < 32; i++) {
                    float v = tb[i];
                    h0 = fmaf(v, W1l[(32 + i) * 64 + lane], h0);
                    h1 = fmaf(v, W1l[(32 + i) * 64 + 32 + lane], h1);
                }
                // LN + relu
                float m = warp_sum(h0 + h1) * (1.0f / 64.0f);
                float d0 = h0 - m, d1 = h1 - m;
                float var = warp_sum(d0 * d0 + d1 * d1) * (1.0f / 64.0f);
                float inv = rsqrtf(var + 1e-5f);
                float a0 = fmaxf(d0 * inv * sg[l * 64 + lane] + sbe[l * 64 + lane], 0.0f);
                float a1 = fmaxf(d1 * inv * sg[l * 64 + 32 + lane] + sbe[l * 64 + 32 + lane], 0.0f);
                wch[lane] = a0; wch[lane + 32] = a1;
                __syncwarp();
                // cv = ch @ W2 + b2, l2norm, gate
                float t = sb2[l * 32 + lane];
#pragma unroll
                for (int hh = 0; hh < 64; hh++) t = fmaf(wch[hh], W2l[hh * 32 + lane], t);
                float nrm = sqrtf(warp_sum(t * t));
                t = scale * (t / fmaxf(nrm, 1e-12f));
                out[(((size_t)b * 7 + l) * 3 + p) * 32 + lane] = t;
                __syncwarp();
            }
        }
        __syncwarp();
    }
}

// ============================================================================
extern "C" void kernel_launch(void* const* d_in, const int* in_sizes, int n_in,
                              void* d_out, int out_size)
{
    const float* z      = (const float*)d_in[0];
    const float* gen_W1 = (const float*)d_in[1];
    const float* gen_b1 = (const float*)d_in[2];
    const float* gen_g  = (const float*)d_in[3];
    const float* gen_be = (const float*)d_in[4];
    const float* gen_W2 = (const float*)d_in[5];
    const float* gen_b2 = (const float*)d_in[6];
    const float* cf_W1  = (const float*)d_in[7];
    const float* cf_b1  = (const float*)d_in[8];
    const float* cf_W2  = (const float*)d_in[9];
    const float* cf_b2  = (const float*)d_in[10];
    const float* g_W    = (const float*)d_in[11];
    const float* g_b    = (const float*)d_in[12];
    const float* c_W1   = (const float*)d_in[13];
    const float* c_b1   = (const float*)d_in[14];
    const float* c_g    = (const float*)d_in[15];
    const float* c_be   = (const float*)d_in[16];
    const float* c_W2   = (const float*)d_in[17];
    const float* c_b2   = (const float*)d_in[18];

    float* out      = (float*)d_out;                       // composed [B,7,3,32]
    float* out_conf = out + (size_t)B_TOTAL * 672;         // comp_conf [B,7,3]

    cudaFuncSetAttribute(colony_k1, cudaFuncAttributeMaxDynamicSharedMemorySize, K1_SMEM);
    cudaFuncSetAttribute(colony_k2, cudaFuncAttributeMaxDynamicSharedMemorySize, K2_SMEM);

    colony_k1<<<1184, 512, K1_SMEM>>>(z, gen_W1, gen_b1, gen_g, gen_be, gen_W2, gen_b2,
                                      cf_W1, cf_b1, cf_W2, cf_b2, g_W, g_b, out_conf);
    colony_k2<<<1184, 512, K2_SMEM>>>(c_W1, c_b1, c_g, c_be, c_W2, c_b2, out);
}

// round 2
// speedup vs baseline: 1.3762x; 1.3762x over previous
#include <cuda_runtime.h>
#include <math.h>

#define B_TOTAL 65536
#define NL 7
#define ZDIM 14
#define DDIM 32
#define HDIM 64

// ---- scratch (static device globals: allocation-free rule) ----
__device__ __align__(16) float g_traces[(size_t)B_TOTAL * NL * DDIM];   // 58.7 MB
__device__ float g_gates[(size_t)B_TOTAL * NL];                         // 1.8 MB

// Fano ordered pairs: src = FANO[l][p], par = FANO[l][(p+1)%3]
__constant__ int FSRC[21] = {0,1,2, 0,3,4, 0,5,6, 1,3,5, 1,4,6, 2,3,6, 2,4,5};
__constant__ int FPAR[21] = {1,2,0, 3,4,0, 5,6,0, 3,5,1, 4,6,1, 3,6,2, 4,5,2};

__device__ __forceinline__ float warp_sum(float v) {
#pragma unroll
    for (int o = 16; o > 0; o >>= 1) v += __shfl_xor_sync(0xffffffffu, v, o);
    return v;
}

__device__ __forceinline__ float fast_sigmoid(float x) {
    return __fdividef(1.0f, 1.0f + __expf(-x));
}

__device__ __forceinline__ float colony_act(int c, float x) {
    switch (c) {
        case 0: return fmaxf(x, 0.0f);                                   // relu
        case 1: {                                                         // tanh
            float e = __expf(2.0f * x);
            return 1.0f - __fdividef(2.0f, e + 1.0f);
        }
        case 2: return 0.5f * x * (1.0f + erff(x * 0.7071067811865476f)); // exact gelu
        case 3: return x * fast_sigmoid(x);                               // silu
        case 4: return fmaxf(x, 0.0f) + log1pf(__expf(-fabsf(x)));        // softplus
        case 5: return fast_sigmoid(x);                                   // sigmoid
        default: return fminf(fmaxf(x, -1.0f), 1.0f);                     // clip
    }
}

// ============================================================================
// Kernel 1: trace generator + confidence + gates + comp_conf   (2 batches/warp)
// ============================================================================
#define K1_WSZ 27344
#define K1_SCR 808
#define K1_WARPS 16
#define K1_SMEM ((K1_WSZ + K1_WARPS * K1_SCR) * 4)

__global__ void __launch_bounds__(512, 1)
colony_k1(const float* __restrict__ z,
          const float* __restrict__ gen_W1, const float* __restrict__ gen_b1,
          const float* __restrict__ gen_g,  const float* __restrict__ gen_be,
          const float* __restrict__ gen_W2, const float* __restrict__ gen_b2,
          const float* __restrict__ cf_W1,  const float* __restrict__ cf_b1,
          const float* __restrict__ cf_W2,  const float* __restrict__ cf_b2,
          const float* __restrict__ gw,     const float* __restrict__ gb,
          float* __restrict__ out_conf)
{
    extern __shared__ float sm[];
    float* sW1  = sm;            // 6272
    float* sb1  = sW1  + 6272;   // 448
    float* sg   = sb1  + 448;    // 448
    float* sbe  = sg   + 448;    // 448
    float* sW2  = sbe  + 448;    // 14336
    float* sb2  = sW2  + 14336;  // 224
    float* scW1 = sb2  + 224;    // 3136
    float* scb1 = scW1 + 3136;   // 224
    float* scW2 = scb1 + 224;    // 224
    float* scb2 = scW2 + 224;    // 8
    float* sgW  = scb2 + 8;      // 1568
    float* sgb  = sgW  + 1568;   // 8
    float* sscr = sgb  + 8;

    const int tid = threadIdx.x;
    for (int i = tid; i < 6272;  i += blockDim.x) sW1[i]  = gen_W1[i];
    for (int i = tid; i < 448;   i += blockDim.x) sb1[i]  = gen_b1[i];
    for (int i = tid; i < 448;   i += blockDim.x) sg[i]   = gen_g[i];
    for (int i = tid; i < 448;   i += blockDim.x) sbe[i]  = gen_be[i];
    for (int i = tid; i < 14336; i += blockDim.x) sW2[i]  = gen_W2[i];
    for (int i = tid; i < 224;   i += blockDim.x) sb2[i]  = gen_b2[i];
    for (int i = tid; i < 3136;  i += blockDim.x) scW1[i] = cf_W1[i];
    for (int i = tid; i < 224;   i += blockDim.x) scb1[i] = cf_b1[i];
    for (int i = tid; i < 224;   i += blockDim.x) scW2[i] = cf_W2[i];
    for (int i = tid; i < 7;     i += blockDim.x) scb2[i] = cf_b2[i];
    for (int i = tid; i < 1568;  i += blockDim.x) sgW[i]  = gw[i];
    for (int i = tid; i < 7;     i += blockDim.x) sgb[i]  = gb[i];
    __syncthreads();

    const int wid  = tid >> 5;
    const int lane = tid & 31;
    float* wscr  = sscr + wid * K1_SCR;
    float* wzA   = wscr;         // 100 (98 used)
    float* wzB   = wzA + 100;    // 100
    float* waA   = wzB + 100;    // 64
    float* waB   = waA + 64;     // 64
    float* wtrA  = waB + 64;     // 224
    float* wtrB  = wtrA + 224;   // 224
    float* wcfA  = wtrB + 224;   // 8
    float* wcfB  = wcfA + 8;     // 8
    float* wgtA  = wcfB + 8;     // 8
    float* wgtB  = wgtA + 8;     // 8

    const int warps_per_block = blockDim.x >> 5;
    const int gwarp = blockIdx.x * warps_per_block + wid;
    const int nwarp = gridDim.x * warps_per_block;

    for (int b0 = gwarp * 2; b0 < B_TOTAL; b0 += nwarp * 2) {
        const int bA = b0, bB = b0 + 1;
        // load z for both batches (float2: 98 floats = 49 float2, 8B aligned)
        const float2* zA = (const float2*)(z + (size_t)bA * 98);
        const float2* zB = (const float2*)(z + (size_t)bB * 98);
        for (int i = lane; i < 49; i += 32) {
            ((float2*)wzA)[i] = zA[i];
            ((float2*)wzB)[i] = zB[i];
        }
        __syncwarp();

#pragma unroll
        for (int c = 0; c < NL; c++) {
            // ---- h = z @ W1 + b1 : lane owns cols (2*lane, 2*lane+1) ----
            float2 bias = *(const float2*)&sb1[c * 64 + 2 * lane];
            float2 hA = bias, hB = bias;
            const float* w1c = sW1 + c * (14 * 64);
            const float* zcA = wzA + c * 14;
            const float* zcB = wzB + c * 14;
#pragma unroll
            for (int q = 0; q < 14; q++) {
                float2 w = *(const float2*)&w1c[q * 64 + 2 * lane];
                float va = zcA[q], vb = zcB[q];
                hA.x = fmaf(va, w.x, hA.x); hA.y = fmaf(va, w.y, hA.y);
                hB.x = fmaf(vb, w.x, hB.x); hB.y = fmaf(vb, w.y, hB.y);
            }
            // ---- LayerNorm over 64 + colony activation ----
            float mA = warp_sum(hA.x + hA.y) * (1.0f / 64.0f);
            float mB = warp_sum(hB.x + hB.y) * (1.0f / 64.0f);
            float dAx = hA.x - mA, dAy = hA.y - mA;
            float dBx = hB.x - mB, dBy = hB.y - mB;
            float vA = warp_sum(dAx * dAx + dAy * dAy) * (1.0f / 64.0f);
            float vB = warp_sum(dBx * dBx + dBy * dBy) * (1.0f / 64.0f);
            float iA = rsqrtf(vA + 1e-5f), iB = rsqrtf(vB + 1e-5f);
            float2 gg = *(const float2*)&sg[c * 64 + 2 * lane];
            float2 bb = *(const float2*)&sbe[c * 64 + 2 * lane];
            float2 aA, aB;
            aA.x = colony_act(c, dAx * iA * gg.x + bb.x);
            aA.y = colony_act(c, dAy * iA * gg.y + bb.y);
            aB.x = colony_act(c, dBx * iB * gg.x + bb.x);
            aB.y = colony_act(c, dBy * iB * gg.y + bb.y);
            *(float2*)&waA[2 * lane] = aA;
            *(float2*)&waB[2 * lane] = aB;
            __syncwarp();
            // ---- traces = a @ W2 + b2 : lane owns col lane; weight reused ----
            float tA = sb2[c * 32 + lane];
            float tB = tA;
            const float* w2c = sW2 + c * (64 * 32);
#pragma unroll
            for (int i0 = 0; i0 < 64; i0 += 4) {
                float4 vA4 = *(const float4*)&waA[i0];
                float4 vB4 = *(const float4*)&waB[i0];
#pragma unroll
                for (int q = 0; q < 4; q++) {
                    float w = w2c[(i0 + q) * 32 + lane];
                    tA = fmaf(((const float*)&vA4)[q], w, tA);
                    tB = fmaf(((const float*)&vB4)[q], w, tB);
                }
            }
            float nA = sqrtf(warp_sum(tA * tA));
            float nB = sqrtf(warp_sum(tB * tB));
            tA = __fdividef(tA, fmaxf(nA, 1e-12f));
            tB = __fdividef(tB, fmaxf(nB, 1e-12f));
            wtrA[c * 32 + lane] = tA;
            wtrB[c * 32 + lane] = tB;
            g_traces[(size_t)bA * 224 + c * 32 + lane] = tA;
            g_traces[(size_t)bB * 224 + c * 32 + lane] = tB;
            // ---- confidence head: 32 cols, lane-owned, shared weights ----
            float hcA = scb1[c * 32 + lane];
            float hcB = hcA;
            const float* cw1 = scW1 + c * (14 * 32);
#pragma unroll
            for (int q = 0; q < 14; q++) {
                float w = cw1[q * 32 + lane];
                hcA = fmaf(zcA[q], w, hcA);
                hcB = fmaf(zcB[q], w, hcB);
            }
            hcA = fmaxf(hcA, 0.0f); hcB = fmaxf(hcB, 0.0f);
            float w2v = scW2[c * 32 + lane];
            float sA = warp_sum(hcA * w2v);
            float sB = warp_sum(hcB * w2v);
            if (lane == 0) {
                wcfA[c] = fast_sigmoid(sA + scb2[c]);
                wcfB[c] = fast_sigmoid(sB + scb2[c]);
            }
            __syncwarp();
        }

        // ---- gates = sigmoid(traces_flat @ gW + gb) ----
#pragma unroll
        for (int l = 0; l < NL; l++) {
            float pA = 0.0f, pB = 0.0f;
#pragma unroll
            for (int k = 0; k < 7; k++) {
                int i = lane + 32 * k;
                float w = sgW[i * 7 + l];
                pA = fmaf(wtrA[i], w, pA);
                pB = fmaf(wtrB[i], w, pB);
            }
            pA = warp_sum(pA);
            pB = warp_sum(pB);
            if (lane == 0) {
                wgtA[l] = fast_sigmoid(pA + sgb[l]);
                wgtB[l] = fast_sigmoid(pB + sgb[l]);
            }
        }
        __syncwarp();
        if (lane < 7) {
            g_gates[(size_t)bA * 7 + lane] = wgtA[lane];
            g_gates[(size_t)bB * 7 + lane] = wgtB[lane];
        }
        if (lane < 21) {
            int l = lane / 3;
            int s = FSRC[lane], p = FPAR[lane];
            float gA = wgtA[l], gB = wgtB[l];
            out_conf[(size_t)bA * 21 + lane] = (gA >= 0.3f) ? wcfA[s] * wcfA[p] * gA : 0.0f;
            out_conf[(size_t)bB * 21 + lane] = (gB >= 0.3f) ? wcfB[s] * wcfB[p] * gB : 0.0f;
        }
        __syncwarp();
    }
}

// ============================================================================
// Kernel 2: line composers  (2 batches/warp, float2 weights, float4 inputs)
// ============================================================================
#define K2_WSZ 44576
#define K2_SCR 592
#define K2_WARPS 16
#define K2_SMEM ((K2_WSZ + K2_WARPS * K2_SCR) * 4)

__global__ void __launch_bounds__(512, 1)
colony_k2(const float* __restrict__ cW1, const float* __restrict__ cb1,
          const float* __restrict__ cg,  const float* __restrict__ cbe,
          const float* __restrict__ cW2, const float* __restrict__ cb2,
          float* __restrict__ out)
{
    extern __shared__ float sm[];
    float* sW1 = sm;            // 28672
    float* sb1 = sW1 + 28672;   // 448
    float* sg  = sb1 + 448;     // 448
    float* sbe = sg  + 448;     // 448
    float* sW2 = sbe + 448;     // 14336
    float* sb2 = sW2 + 14336;   // 224
    float* sscr = sb2 + 224;

    const int tid = threadIdx.x;
    for (int i = tid; i < 28672; i += blockDim.x) sW1[i] = cW1[i];
    for (int i = tid; i < 448;   i += blockDim.x) sb1[i] = cb1[i];
    for (int i = tid; i < 448;   i += blockDim.x) sg[i]  = cg[i];
    for (int i = tid; i < 448;   i += blockDim.x) sbe[i] = cbe[i];
    for (int i = tid; i < 14336; i += blockDim.x) sW2[i] = cW2[i];
    for (int i = tid; i < 224;   i += blockDim.x) sb2[i] = cb2[i];
    __syncthreads();

    const int wid  = tid >> 5;
    const int lane = tid & 31;
    float* wscr = sscr + wid * K2_SCR;
    float* wtrA = wscr;          // 224
    float* wtrB = wtrA + 224;    // 224
    float* wchA = wtrB + 224;    // 64
    float* wchB = wchA + 64;     // 64
    float* wgA  = wchB + 64;     // 8
    float* wgB  = wgA + 8;       // 8

    const int warps_per_block = blockDim.x >> 5;
    const int gwarp = blockIdx.x * warps_per_block + wid;
    const int nwarp = gridDim.x * warps_per_block;

    for (int b0 = gwarp * 2; b0 < B_TOTAL; b0 += nwarp * 2) {
        const int bA = b0, bB = b0 + 1;
        const float4* gA4 = (const float4*)(g_traces + (size_t)bA * 224);
        const float4* gB4 = (const float4*)(g_traces + (size_t)bB * 224);
        for (int i = lane; i < 56; i += 32) {
            ((float4*)wtrA)[i] = gA4[i];
            ((float4*)wtrB)[i] = gB4[i];
        }
        if (lane < 7) {
            wgA[lane] = g_gates[(size_t)bA * 7 + lane];
            wgB[lane] = g_gates[(size_t)bB * 7 + lane];
        }
        __syncwarp();

#pragma unroll
        for (int l = 0; l < NL; l++) {
            float glA = wgA[l], glB = wgB[l];
            float scA = (glA >= 0.3f) ? glA : 0.0f;
            float scB = (glB >= 0.3f) ? glB : 0.0f;
            const float* W1l = sW1 + l * (64 * 64);
            const float* W2l = sW2 + l * (64 * 32);
            float2 bias1 = *(const float2*)&sb1[l * 64 + 2 * lane];
            float2 gg = *(const float2*)&sg[l * 64 + 2 * lane];
            float2 bb = *(const float2*)&sbe[l * 64 + 2 * lane];
            float b2v = sb2[l * 32 + lane];
#pragma unroll
            for (int p = 0; p < 3; p++) {
                const int sc = FSRC[l * 3 + p];
                const int pc = FPAR[l * 3 + p];
                const float* inA0 = wtrA + sc * 32;
                const float* inB0 = wtrB + sc * 32;
                const float* inA1 = wtrA + pc * 32;
                const float* inB1 = wtrB + pc * 32;
                // ---- stage 1: h = [src,par] @ W1 + b1, lane owns cols 2l,2l+1 ----
                float2 hA = bias1, hB = bias1;
#pragma unroll
                for (int i0 = 0; i0 < 32; i0 += 4) {
                    float4 vA4 = *(const float4*)&inA0[i0];
                    float4 vB4 = *(const float4*)&inB0[i0];
#pragma unroll
                    for (int q = 0; q < 4; q++) {
                        float2 w = *(const float2*)&W1l[(i0 + q) * 64 + 2 * lane];
                        float va = ((const float*)&vA4)[q];
                        float vb = ((const float*)&vB4)[q];
                        hA.x = fmaf(va, w.x, hA.x); hA.y = fmaf(va, w.y, hA.y);
                        hB.x = fmaf(vb, w.x, hB.x); hB.y = fmaf(vb, w.y, hB.y);
                    }
                }
#pragma unroll
                for (int i0 = 0; i0 < 32; i0 += 4) {
                    float4 vA4 = *(const float4*)&inA1[i0];
                    float4 vB4 = *(const float4*)&inB1[i0];
#pragma unroll
                    for (int q = 0; q < 4; q++) {
                        float2 w = *(const float2*)&W1l[(32 + i0 + q) * 64 + 2 * lane];
                        float va = ((const float*)&vA4)[q];
                        float vb = ((const float*)&vB4)[q];
                        hA.x = fmaf(va, w.x, hA.x); hA.y = fmaf(va, w.y, hA.y);
                        hB.x = fmaf(vb, w.x, hB.x); hB.y = fmaf(vb, w.y, hB.y);
                    }
                }
                // ---- LN + ReLU ----
                float mA = warp_sum(hA.x + hA.y) * (1.0f / 64.0f);
                float mB = warp_sum(hB.x + hB.y) * (1.0f / 64.0f);
                float dAx = hA.x - mA, dAy = hA.y - mA;
                float dBx = hB.x - mB, dBy = hB.y - mB;
                float vA = warp_sum(dAx * dAx + dAy * dAy) * (1.0f / 64.0f);
                float vB = warp_sum(dBx * dBx + dBy * dBy) * (1.0f / 64.0f);
                float iA = rsqrtf(vA + 1e-5f), iB = rsqrtf(vB + 1e-5f);
                float2 aA, aB;
                aA.x = fmaxf(dAx * iA * gg.x + bb.x, 0.0f);
                aA.y = fmaxf(dAy * iA * gg.y + bb.y, 0.0f);
                aB.x = fmaxf(dBx * iB * gg.x + bb.x, 0.0f);
                aB.y = fmaxf(dBy * iB * gg.y + bb.y, 0.0f);
                *(float2*)&wchA[2 * lane] = aA;
                *(float2*)&wchB[2 * lane] = aB;
                __syncwarp();
                // ---- stage 2: cv = a @ W2 + b2, l2norm, gate ----
                float tA = b2v, tB = b2v;
#pragma unroll
                for (int i0 = 0; i0 < 64; i0 += 4) {
                    float4 vA4 = *(const float4*)&wchA[i0];
                    float4 vB4 = *(const float4*)&wchB[i0];
#pragma unroll
                    for (int q = 0; q < 4; q++) {
                        float w = W2l[(i0 + q) * 32 + lane];
                        tA = fmaf(((const float*)&vA4)[q], w, tA);
                        tB = fmaf(((const float*)&vB4)[q], w, tB);
                    }
                }
                float nA = sqrtf(warp_sum(tA * tA));
                float nB = sqrtf(warp_sum(tB * tB));
                tA = scA * __fdividef(tA, fmaxf(nA, 1e-12f));
                tB = scB * __fdividef(tB, fmaxf(nB, 1e-12f));
                out[(((size_t)bA * 7 + l) * 3 + p) * 32 + lane] = tA;
                out[(((size_t)bB * 7 + l) * 3 + p) * 32 + lane] = tB;
                __syncwarp();
            }
        }
    }
}

// ============================================================================
extern "C" void kernel_launch(void* const* d_in, const int* in_sizes, int n_in,
                              void* d_out, int out_size)
{
    const float* z      = (const float*)d_in[0];
    const float* gen_W1 = (const float*)d_in[1];
    const float* gen_b1 = (const float*)d_in[2];
    const float* gen_g  = (const float*)d_in[3];
    const float* gen_be = (const float*)d_in[4];
    const float* gen_W2 = (const float*)d_in[5];
    const float* gen_b2 = (const float*)d_in[6];
    const float* cf_W1  = (const float*)d_in[7];
    const float* cf_b1  = (const float*)d_in[8];
    const float* cf_W2  = (const float*)d_in[9];
    const float* cf_b2  = (const float*)d_in[10];
    const float* g_W    = (const float*)d_in[11];
    const float* g_b    = (const float*)d_in[12];
    const float* c_W1   = (const float*)d_in[13];
    const float* c_b1   = (const float*)d_in[14];
    const float* c_g    = (const float*)d_in[15];
    const float* c_be   = (const float*)d_in[16];
    const float* c_W2   = (const float*)d_in[17];
    const float* c_b2   = (const float*)d_in[18];

    float* out      = (float*)d_out;                       // composed [B,7,3,32]
    float* out_conf = out + (size_t)B_TOTAL * 672;         // comp_conf [B,7,3]

    cudaFuncSetAttribute(colony_k1, cudaFuncAttributeMaxDynamicSharedMemorySize, K1_SMEM);
    cudaFuncSetAttribute(colony_k2, cudaFuncAttributeMaxDynamicSharedMemorySize, K2_SMEM);

    colony_k1<<<148, 512, K1_SMEM>>>(z, gen_W1, gen_b1, gen_g, gen_be, gen_W2, gen_b2,
                                     cf_W1, cf_b1, cf_W2, cf_b2, g_W, g_b, out_conf);
    colony_k2<<<148, 512, K2_SMEM>>>(c_W1, c_b1, c_g, c_be, c_W2, c_b2, out);
}